// round 3
// baseline (speedup 1.0000x reference)
#include <cuda_runtime.h>

#define NN 100000
#define NE 1600000
#define NG 1000
#define NBLK 98   // ceil(NN/1024)

// ---- static scratch ----
__device__ int    g_cnt[2][NN];
__device__ int    g_off[2][NN + 1];
__device__ int    g_rank[2][NE];
__device__ int    g_src[2][NE];
__device__ int    g_state[2][NBLK];
__device__ float4 g_y1[2][NN * 8];
__device__ float4 g_y2[2][NN * 8];
__device__ float  g_C1[1024], g_C2[1024], g_D1[1024], g_D2[1024];
__device__ float  g_bp[32], g_e1[32], g_e2[32], g_v[32], g_c[1];

// ================= init =================

__global__ void k_init(float* __restrict__ out, const float* __restrict__ lin_b) {
    int i = blockIdx.x * blockDim.x + threadIdx.x;
    if (i < NG) out[i] = lin_b[0];
    if (i < NN) { g_cnt[0][i] = 0; g_cnt[1][i] = 0; }
    if (i < 2 * NBLK) ((int*)g_state)[i] = 0;
}

// ================= hist (stores per-edge rank; fill becomes atomic-free) =================

__global__ void k_hist(const int* __restrict__ el, const int* __restrict__ eg) {
    int e = blockIdx.x * blockDim.x + threadIdx.x;
    if (e >= NE) return;
    int set = blockIdx.y;
    const int* ei = set ? eg : el;
    g_rank[set][e] = atomicAdd(&g_cnt[set][ei[NE + e]], 1);
}

// ================= single-kernel scan (decoupled lookback; all 196 blocks resident) =================

__global__ void k_scan() {
    __shared__ int swarp[32];
    __shared__ int s_excl;
    int se = blockIdx.y, blk = blockIdx.x;
    int i = blk * 1024 + threadIdx.x;
    int lane = threadIdx.x & 31, wid = threadIdx.x >> 5;
    int v = (i < NN) ? g_cnt[se][i] : 0;
    int incl = v;
#pragma unroll
    for (int d = 1; d < 32; d <<= 1) {
        int t = __shfl_up_sync(0xffffffffu, incl, d);
        if (lane >= d) incl += t;
    }
    if (lane == 31) swarp[wid] = incl;
    __syncthreads();
    if (wid == 0) {
        int winc = swarp[lane];
#pragma unroll
        for (int d = 1; d < 32; d <<= 1) {
            int t = __shfl_up_sync(0xffffffffu, winc, d);
            if (lane >= d) winc += t;
        }
        swarp[lane] = winc;
    }
    __syncthreads();
    int wexcl = (wid == 0) ? 0 : swarp[wid - 1];
    int btotal = swarp[31];
    int local_incl = wexcl + incl;
    if (threadIdx.x == 0) {
        if (blk == 0) {
            atomicExch(&g_state[se][0], (btotal << 2) | 2);
            s_excl = 0;
        } else {
            atomicExch(&g_state[se][blk], (btotal << 2) | 1);
            int excl = 0, j = blk - 1;
            while (true) {
                int s = atomicAdd(&g_state[se][j], 0);
                int f = s & 3;
                if (f == 0) continue;
                excl += (s >> 2);
                if (f == 2) break;
                j--;
            }
            atomicExch(&g_state[se][blk], ((excl + btotal) << 2) | 2);
            s_excl = excl;
        }
    }
    __syncthreads();
    int ex = s_excl + local_incl - v;
    if (i < NN) {
        g_off[se][i] = ex;
        if (i == NN - 1) g_off[se][NN] = ex + v;
    }
}

// ================= fill (atomic-free scatter using stored ranks) =================

__global__ void k_fill(const int* __restrict__ el, const int* __restrict__ eg) {
    int e = blockIdx.x * blockDim.x + threadIdx.x;
    if (e >= NE) return;
    int set = blockIdx.y;
    const int* ei = set ? eg : el;
    int src = ei[e], dst = ei[NE + e];
    g_src[set][g_off[set][dst] + g_rank[set][e]] = src;
}

// ================= compose fused linear chains (no relu between => matrices multiply) =================

__global__ void k_compose(
    const float* __restrict__ w11b, const float* __restrict__ w12b,
    const float* __restrict__ m1a,  const float* __restrict__ m1b,
    const float* __restrict__ w21a, const float* __restrict__ w22a,
    const float* __restrict__ m2b,
    const float* __restrict__ b11b, const float* __restrict__ b12b,
    const float* __restrict__ m1ab, const float* __restrict__ m1bb,
    const float* __restrict__ m2bb, const float* __restrict__ linW)
{
    __shared__ float s11b[1024], s12b[1024], sm1a[2048], sm1b[1024], s21a[1024], s22a[1024];
    int tid = threadIdx.x;
    s11b[tid] = w11b[tid]; s12b[tid] = w12b[tid]; sm1b[tid] = m1b[tid];
    s21a[tid] = w21a[tid]; s22a[tid] = w22a[tid];
    sm1a[tid] = m1a[tid];  sm1a[tid + 1024] = m1a[tid + 1024];
    __syncthreads();
    int k = tid >> 5, o = tid & 31;
    float c1 = 0.f, c2 = 0.f, d1 = 0.f, d2 = 0.f;
#pragma unroll
    for (int j = 0; j < 32; j++) {
        c1 = fmaf(s11b[k * 32 + j], sm1a[j * 32 + o], c1);          // W11b @ M1a_top
        c2 = fmaf(s12b[k * 32 + j], sm1a[(32 + j) * 32 + o], c2);   // W12b @ M1a_bot
        d1 = fmaf(sm1b[k * 32 + j], s21a[j * 32 + o], d1);          // M1b @ W21a
        d2 = fmaf(sm1b[k * 32 + j], s22a[j * 32 + o], d2);          // M1b @ W22a
    }
    g_C1[tid] = c1; g_C2[tid] = c2; g_D1[tid] = d1; g_D2[tid] = d2;
    if (k == 0) {
        float bp = m1ab[o], e1 = 0.f, e2 = 0.f;
        for (int j = 0; j < 32; j++) {
            bp += b11b[j] * sm1a[j * 32 + o] + b12b[j] * sm1a[(32 + j) * 32 + o];
            e1 += m1bb[j] * s21a[j * 32 + o];
            e2 += m1bb[j] * s22a[j * 32 + o];
        }
        g_bp[o] = bp; g_e1[o] = e1; g_e2[o] = e2;
    }
    if (o == 0) {
        float v = 0.f;
        for (int j = 0; j < 32; j++) v += m2b[k * 32 + j] * linW[j];
        g_v[k] = v;
    }
    if (tid == 0) {
        float c = 0.f;
        for (int j = 0; j < 32; j++) c += m2bb[j] * linW[j];
        g_c[0] = c;
    }
}

// ================= vectorized cooperative gather: 4 edges per LDG.128 =================
// lane = sub(edge mod 4) * 8 + chunk(float4 within row). Returns channel `lane`'s sum.
__device__ __forceinline__ float gather4(const float4* __restrict__ y4, const int* __restrict__ src,
                                         int b, int e, int lane, float* __restrict__ red) {
    int sub = lane >> 3, chunk = lane & 7;
    float4 a0 = make_float4(0.f, 0.f, 0.f, 0.f);
    float4 a1 = make_float4(0.f, 0.f, 0.f, 0.f);
    int p = b + sub;
    for (; p + 4 < e; p += 8) {
        int s0 = __ldg(&src[p]);
        int s1 = __ldg(&src[p + 4]);
        float4 v0 = __ldg(&y4[s0 * 8 + chunk]);
        float4 v1 = __ldg(&y4[s1 * 8 + chunk]);
        a0.x += v0.x; a0.y += v0.y; a0.z += v0.z; a0.w += v0.w;
        a1.x += v1.x; a1.y += v1.y; a1.z += v1.z; a1.w += v1.w;
    }
    if (p < e) {
        int s0 = __ldg(&src[p]);
        float4 v0 = __ldg(&y4[s0 * 8 + chunk]);
        a0.x += v0.x; a0.y += v0.y; a0.z += v0.z; a0.w += v0.w;
    }
    a0.x += a1.x; a0.y += a1.y; a0.z += a1.z; a0.w += a1.w;
#pragma unroll
    for (int m = 8; m <= 16; m <<= 1) {
        a0.x += __shfl_xor_sync(0xffffffffu, a0.x, m);
        a0.y += __shfl_xor_sync(0xffffffffu, a0.y, m);
        a0.z += __shfl_xor_sync(0xffffffffu, a0.z, m);
        a0.w += __shfl_xor_sync(0xffffffffu, a0.w, m);
    }
    __syncwarp();
    if (sub == 0) ((float4*)red)[chunk] = a0;   // channels chunk*4..chunk*4+3
    __syncwarp();
    float r = red[lane];
    __syncwarp();
    return r;
}

// ================= matvec helpers =================

__device__ __forceinline__ float mv32r(const float wr[32], float v) {
    float u = 0.f;
#pragma unroll
    for (int k = 0; k < 32; k++)
        u = fmaf(__shfl_sync(0xffffffffu, v, k), wr[k], u);
    return u;
}

__device__ __forceinline__ void mv32x2(const float* __restrict__ Wa, const float* __restrict__ Wb,
                                       float v, int lane, float& ua, float& ub) {
    ua = 0.f; ub = 0.f;
#pragma unroll
    for (int k = 0; k < 32; k++) {
        float s = __shfl_sync(0xffffffffu, v, k);
        ua = fmaf(s, Wa[k * 32 + lane], ua);
        ub = fmaf(s, Wb[k * 32 + lane], ub);
    }
}

// ================= pre1: y11 = x@c11_W1, y12 = x@c12_W1 =================

__global__ __launch_bounds__(256) void k_pre1(const float* __restrict__ x,
                                              const float* __restrict__ w11a,
                                              const float* __restrict__ w12a) {
    __shared__ float sB[2048];
    for (int t = threadIdx.x; t < 2048; t += 256) sB[t] = w12a[t];
    __syncthreads();
    int gw = (blockIdx.x * 256 + threadIdx.x) >> 5;
    int lane = threadIdx.x & 31;
    float wa[64];
#pragma unroll
    for (int k = 0; k < 64; k++) wa[k] = w11a[k * 32 + lane];
    float2 a = ((const float2*)x)[gw * 32 + lane];   // channels 2*lane, 2*lane+1
    float y1 = 0.f, y2 = 0.f;
#pragma unroll
    for (int k = 0; k < 32; k++) {
        float ax = __shfl_sync(0xffffffffu, a.x, k);
        float ay = __shfl_sync(0xffffffffu, a.y, k);
        y1 = fmaf(ax, wa[2 * k], y1);
        y1 = fmaf(ay, wa[2 * k + 1], y1);
        y2 = fmaf(ax, sB[(2 * k) * 32 + lane], y2);
        y2 = fmaf(ay, sB[(2 * k + 1) * 32 + lane], y2);
    }
    ((float*)g_y1[0])[gw * 32 + lane] = y1;
    ((float*)g_y1[1])[gw * 32 + lane] = y2;
}

// ================= layer 1 (composed): agg -> t -> tm -> y2 pre-transforms =================

__global__ __launch_bounds__(256) void k_layer1(const float* __restrict__ b11a,
                                                const float* __restrict__ b12a) {
    __shared__ float sD1[1024], sD2[1024];
    __shared__ float sb1[32], sb2[32], sbp[32], se1[32], se2[32];
    __shared__ float4 s_red[8][8];
    for (int t = threadIdx.x; t < 1024; t += 256) { sD1[t] = g_D1[t]; sD2[t] = g_D2[t]; }
    if (threadIdx.x < 32) {
        sb1[threadIdx.x] = b11a[threadIdx.x];
        sb2[threadIdx.x] = b12a[threadIdx.x];
        sbp[threadIdx.x] = g_bp[threadIdx.x];
        se1[threadIdx.x] = g_e1[threadIdx.x];
        se2[threadIdx.x] = g_e2[threadIdx.x];
    }
    __syncthreads();
    int gw = (blockIdx.x * 256 + threadIdx.x) >> 5;   // grid exact: gw < NN
    int lane = threadIdx.x & 31;
    int warp = threadIdx.x >> 5;
    float wc1[32], wc2[32];
#pragma unroll
    for (int k = 0; k < 32; k++) { wc1[k] = g_C1[k * 32 + lane]; wc2[k] = g_C2[k * 32 + lane]; }

    float a1 = ((const float*)g_y1[0])[gw * 32 + lane];
    float a2 = ((const float*)g_y1[1])[gw * 32 + lane];
    float acc1 = gather4(g_y1[0], g_src[0], g_off[0][gw], g_off[0][gw + 1], lane, (float*)s_red[warp]);
    float acc2 = gather4(g_y1[1], g_src[1], g_off[1][gw], g_off[1][gw + 1], lane, (float*)s_red[warp]);

    float t1 = fmaxf(a1 + acc1 + sb1[lane], 0.f);
    float t2 = fmaxf(a2 + acc2 + sb2[lane], 0.f);
    float tm = sbp[lane];
#pragma unroll
    for (int k = 0; k < 32; k++) {
        tm = fmaf(__shfl_sync(0xffffffffu, t1, k), wc1[k], tm);
        tm = fmaf(__shfl_sync(0xffffffffu, t2, k), wc2[k], tm);
    }
    tm = fmaxf(tm, 0.f);
    float y21, y22;
    mv32x2(sD1, sD2, tm, lane, y21, y22);
    ((float*)g_y2[0])[gw * 32 + lane] = y21 + se1[lane];
    ((float*)g_y2[1])[gw * 32 + lane] = y22 + se2[lane];
}

// ================= layer 2: agg -> MLP tails -> m2 -> dot(v) -> pool =================

__global__ __launch_bounds__(256) void k_layer2(
    const int* __restrict__ batch, float* __restrict__ out,
    const float* __restrict__ b21a, const float* __restrict__ w21b, const float* __restrict__ b21b,
    const float* __restrict__ b22a, const float* __restrict__ w22b, const float* __restrict__ b22b,
    const float* __restrict__ m2a,  const float* __restrict__ m2ab)
{
    __shared__ float sm2a[2048];
    __shared__ float sb1[32], sb1b[32], sb2[32], sb2b[32], sbm[32], sv[32];
    __shared__ float4 s_red[8][8];
    __shared__ float sc;
    for (int t = threadIdx.x; t < 2048; t += 256) sm2a[t] = m2a[t];
    if (threadIdx.x < 32) {
        sb1[threadIdx.x] = b21a[threadIdx.x]; sb1b[threadIdx.x] = b21b[threadIdx.x];
        sb2[threadIdx.x] = b22a[threadIdx.x]; sb2b[threadIdx.x] = b22b[threadIdx.x];
        sbm[threadIdx.x] = m2ab[threadIdx.x]; sv[threadIdx.x]  = g_v[threadIdx.x];
    }
    if (threadIdx.x == 0) sc = g_c[0];
    __syncthreads();
    int gw = (blockIdx.x * 256 + threadIdx.x) >> 5;
    int lane = threadIdx.x & 31;
    int warp = threadIdx.x >> 5;
    float w1r[32], w2r[32];
#pragma unroll
    for (int k = 0; k < 32; k++) { w1r[k] = w21b[k * 32 + lane]; w2r[k] = w22b[k * 32 + lane]; }

    float a1 = ((const float*)g_y2[0])[gw * 32 + lane];
    float a2 = ((const float*)g_y2[1])[gw * 32 + lane];
    float acc1 = gather4(g_y2[0], g_src[0], g_off[0][gw], g_off[0][gw + 1], lane, (float*)s_red[warp]);
    float acc2 = gather4(g_y2[1], g_src[1], g_off[1][gw], g_off[1][gw + 1], lane, (float*)s_red[warp]);

    float t1 = fmaxf(a1 + acc1 + sb1[lane], 0.f);
    float t2 = fmaxf(a2 + acc2 + sb2[lane], 0.f);
    float x1 = fmaxf(mv32r(w1r, t1) + sb1b[lane], 0.f);
    float x2 = fmaxf(mv32r(w2r, t2) + sb2b[lane], 0.f);
    float tm = sbm[lane];
#pragma unroll
    for (int k = 0; k < 32; k++) {
        tm = fmaf(__shfl_sync(0xffffffffu, x1, k), sm2a[k * 32 + lane], tm);
        tm = fmaf(__shfl_sync(0xffffffffu, x2, k), sm2a[(32 + k) * 32 + lane], tm);
    }
    tm = fmaxf(tm, 0.f);
    float p = tm * sv[lane];
#pragma unroll
    for (int o = 16; o > 0; o >>= 1) p += __shfl_xor_sync(0xffffffffu, p, o);
    if (lane == 0) atomicAdd(&out[batch[gw]], p + sc);
}

// ================= launch =================

extern "C" void kernel_launch(void* const* d_in, const int* in_sizes, int n_in,
                              void* d_out, int out_size) {
    const float* x     = (const float*)d_in[0];
    const int*   el    = (const int*)d_in[1];
    const int*   eg    = (const int*)d_in[2];
    const int*   batch = (const int*)d_in[3];
    const float* W[26];
    for (int i = 0; i < 26; i++) W[i] = (const float*)d_in[4 + i];
    float* out = (float*)d_out;

    k_init<<<(NN + 255) / 256, 256>>>(out, W[25]);

    dim3 ge((NE + 255) / 256, 2);
    k_hist<<<ge, 256>>>(el, eg);

    dim3 gs(NBLK, 2);
    k_scan<<<gs, 1024>>>();

    k_fill<<<ge, 256>>>(el, eg);   // 4th launch — profiled slot

    k_compose<<<1, 1024>>>(W[2], W[6], W[8], W[10], W[12], W[16], W[22],
                           W[3], W[7], W[9], W[11], W[23], W[24]);

    const int NB = NN * 32 / 256;  // 12500, exact
    k_pre1<<<NB, 256>>>(x, W[0], W[4]);

    k_layer1<<<NB, 256>>>(W[1], W[5]);

    k_layer2<<<NB, 256>>>(batch, out,
                          W[13], W[14], W[15],
                          W[17], W[18], W[19],
                          W[20], W[21]);
}

// round 5
// speedup vs baseline: 1.5291x; 1.5291x over previous
#include <cuda_runtime.h>

#define NN 100000
#define NE 1600000
#define NG 1000
#define NBLK 98   // ceil(NN/1024)

// ---- static scratch ----
__device__ int    g_cnt[2][NN];
__device__ int    g_off[2][NN + 1];
__device__ int    g_rank[2][NE];
__device__ int    g_src[2][NE];
__device__ int    g_state[2][NBLK];
__device__ int    g_done[2];
__device__ float4 g_y1[2][NN * 8];
__device__ float4 g_y2[2][NN * 8];
__device__ float  g_T1[NN * 32], g_T2[NN * 32];
__device__ float  g_C1[1024], g_C2[1024], g_D1[1024], g_D2[1024];
__device__ __align__(16) float g_bp[32], g_e1[32], g_e2[32], g_v[32];
__device__ float  g_c[1];

// ================= 1) init + compose (fused) =================

__global__ __launch_bounds__(1024) void k_init_compose(
    float* __restrict__ out, const float* __restrict__ lin_b,
    const float* __restrict__ w11b, const float* __restrict__ w12b,
    const float* __restrict__ m1a,  const float* __restrict__ m1b,
    const float* __restrict__ w21a, const float* __restrict__ w22a,
    const float* __restrict__ m2b,
    const float* __restrict__ b11b, const float* __restrict__ b12b,
    const float* __restrict__ m1ab, const float* __restrict__ m1bb,
    const float* __restrict__ m2bb, const float* __restrict__ linW)
{
    if (blockIdx.x < 98) {
        int i = blockIdx.x * 1024 + threadIdx.x;
        if (i < NG) out[i] = lin_b[0];
        if (i < NN) { g_cnt[0][i] = 0; g_cnt[1][i] = 0; }
        if (i < 2 * NBLK) ((int*)g_state)[i] = 0;
        if (i < 2) g_done[i] = 0;
        return;
    }
    // block 98: compose fused linear chains
    __shared__ float s11b[1024], s12b[1024], sm1a[2048], sm1b[1024], s21a[1024], s22a[1024];
    int tid = threadIdx.x;
    s11b[tid] = w11b[tid]; s12b[tid] = w12b[tid]; sm1b[tid] = m1b[tid];
    s21a[tid] = w21a[tid]; s22a[tid] = w22a[tid];
    sm1a[tid] = m1a[tid];  sm1a[tid + 1024] = m1a[tid + 1024];
    __syncthreads();
    int k = tid >> 5, o = tid & 31;
    float c1 = 0.f, c2 = 0.f, d1 = 0.f, d2 = 0.f;
#pragma unroll
    for (int j = 0; j < 32; j++) {
        c1 = fmaf(s11b[k * 32 + j], sm1a[j * 32 + o], c1);          // W11b @ M1a_top
        c2 = fmaf(s12b[k * 32 + j], sm1a[(32 + j) * 32 + o], c2);   // W12b @ M1a_bot
        d1 = fmaf(sm1b[k * 32 + j], s21a[j * 32 + o], d1);          // M1b @ W21a
        d2 = fmaf(sm1b[k * 32 + j], s22a[j * 32 + o], d2);          // M1b @ W22a
    }
    g_C1[tid] = c1; g_C2[tid] = c2; g_D1[tid] = d1; g_D2[tid] = d2;
    if (k == 0) {
        float bp = m1ab[o], e1 = 0.f, e2 = 0.f;
        for (int j = 0; j < 32; j++) {
            bp += b11b[j] * sm1a[j * 32 + o] + b12b[j] * sm1a[(32 + j) * 32 + o];
            e1 += m1bb[j] * s21a[j * 32 + o];
            e2 += m1bb[j] * s22a[j * 32 + o];
        }
        g_bp[o] = bp; g_e1[o] = e1; g_e2[o] = e2;
    }
    if (o == 0) {
        float v = 0.f;
        for (int j = 0; j < 32; j++) v += m2b[k * 32 + j] * linW[j];
        g_v[k] = v;
    }
    if (tid == 0) {
        float c = 0.f;
        for (int j = 0; j < 32; j++) c += m2bb[j] * linW[j];
        g_c[0] = c;
    }
}

// ================= 2) hist + pre-transform (fused via grid.y) =================

__global__ __launch_bounds__(256) void k_hist_pre1(
    const int* __restrict__ el, const int* __restrict__ eg,
    const float* __restrict__ x,
    const float* __restrict__ w11a, const float* __restrict__ w12a)
{
    __shared__ float sX[32 * 68];
    __shared__ float sW1[2048], sW2[2048];

    if (blockIdx.y < 2) {
        int e = blockIdx.x * 256 + threadIdx.x;
        if (e >= NE) return;
        int set = blockIdx.y;
        const int* ei = set ? eg : el;
        g_rank[set][e] = atomicAdd(&g_cnt[set][ei[NE + e]], 1);
        return;
    }
    if (blockIdx.x >= 3125) return;
    int tid = threadIdx.x;
    const float4* gx4 = (const float4*)x + blockIdx.x * 512;
    const float4* gw1 = (const float4*)w11a;
    const float4* gw2 = (const float4*)w12a;
#pragma unroll
    for (int r = 0; r < 2; r++) {
        int i = tid + r * 256;
        float4 v = gx4[i];
        int flat = i * 4, n = flat >> 6, kk = flat & 63;
        *(float4*)(sX + n * 68 + kk) = v;
        ((float4*)sW1)[i] = gw1[i];
        ((float4*)sW2)[i] = gw2[i];
    }
    __syncthreads();

    int w = tid >> 5, lane = tid & 31;
    int nsub = lane >> 3, o4 = lane & 7;
    int n = w * 4 + nsub;
    float4 a1 = make_float4(0.f, 0.f, 0.f, 0.f);
    float4 a2 = make_float4(0.f, 0.f, 0.f, 0.f);
    const float4* W1v = (const float4*)sW1;
    const float4* W2v = (const float4*)sW2;
#pragma unroll
    for (int k = 0; k < 64; k++) {
        float xv = sX[n * 68 + k];
        float4 c1 = W1v[k * 8 + o4];
        float4 c2 = W2v[k * 8 + o4];
        a1.x = fmaf(xv, c1.x, a1.x); a1.y = fmaf(xv, c1.y, a1.y);
        a1.z = fmaf(xv, c1.z, a1.z); a1.w = fmaf(xv, c1.w, a1.w);
        a2.x = fmaf(xv, c2.x, a2.x); a2.y = fmaf(xv, c2.y, a2.y);
        a2.z = fmaf(xv, c2.z, a2.z); a2.w = fmaf(xv, c2.w, a2.w);
    }
    int gn = blockIdx.x * 32 + n;
    g_y1[0][gn * 8 + o4] = a1;
    g_y1[1][gn * 8 + o4] = a2;
}

// ================= 3) scan (decoupled lookback) + device barrier + fill =================

__global__ __launch_bounds__(1024, 2) void k_scanfill(const int* __restrict__ el,
                                                      const int* __restrict__ eg) {
    __shared__ int swarp[32];
    __shared__ int s_excl;
    int se = blockIdx.y, blk = blockIdx.x;
    int i = blk * 1024 + threadIdx.x;
    int lane = threadIdx.x & 31, wid = threadIdx.x >> 5;
    int v = (i < NN) ? g_cnt[se][i] : 0;
    int incl = v;
#pragma unroll
    for (int d = 1; d < 32; d <<= 1) {
        int t = __shfl_up_sync(0xffffffffu, incl, d);
        if (lane >= d) incl += t;
    }
    if (lane == 31) swarp[wid] = incl;
    __syncthreads();
    if (wid == 0) {
        int winc = swarp[lane];
#pragma unroll
        for (int d = 1; d < 32; d <<= 1) {
            int t = __shfl_up_sync(0xffffffffu, winc, d);
            if (lane >= d) winc += t;
        }
        swarp[lane] = winc;
    }
    __syncthreads();
    int wexcl = (wid == 0) ? 0 : swarp[wid - 1];
    int btotal = swarp[31];
    int local_incl = wexcl + incl;
    if (threadIdx.x == 0) {
        if (blk == 0) {
            atomicExch(&g_state[se][0], (btotal << 2) | 2);
            s_excl = 0;
        } else {
            atomicExch(&g_state[se][blk], (btotal << 2) | 1);
            int excl = 0, j = blk - 1;
            while (true) {
                int s = atomicAdd(&g_state[se][j], 0);
                int f = s & 3;
                if (f == 0) continue;
                excl += (s >> 2);
                if (f == 2) break;
                j--;
            }
            atomicExch(&g_state[se][blk], ((excl + btotal) << 2) | 2);
            s_excl = excl;
        }
    }
    __syncthreads();
    int ex = s_excl + local_incl - v;
    if (i < NN) {
        g_off[se][i] = ex;
        if (i == NN - 1) g_off[se][NN] = ex + v;
    }
    // ---- device-wide barrier per set (all blocks resident by launch_bounds) ----
    __threadfence();
    __syncthreads();
    if (threadIdx.x == 0) {
        atomicAdd(&g_done[se], 1);
        while (atomicAdd(&g_done[se], 0) < NBLK) { }
    }
    __syncthreads();
    __threadfence();
    // ---- fill (grid-stride, atomic-free via stored ranks) ----
    const int* ei = se ? eg : el;
    for (int e = blk * 1024 + threadIdx.x; e < NE; e += NBLK * 1024) {
        int src = ei[e], dst = ei[NE + e];
        g_src[se][g_off[se][dst] + g_rank[se][e]] = src;
    }
}

// ================= gather: warp = node, 4 edges per LDG.128 =================

__device__ __forceinline__ float gsum(const float4* __restrict__ y4, const int* __restrict__ srcs,
                                      int b, int e, int lane) {
    int sub = lane >> 3, chunk = lane & 7;
    float4 a0 = make_float4(0.f, 0.f, 0.f, 0.f);
    float4 a1 = make_float4(0.f, 0.f, 0.f, 0.f);
    int p = b + sub;
    for (; p + 4 < e; p += 8) {
        int s0 = srcs[p];
        int s1 = srcs[p + 4];
        float4 v0 = y4[s0 * 8 + chunk];
        float4 v1 = y4[s1 * 8 + chunk];
        a0.x += v0.x; a0.y += v0.y; a0.z += v0.z; a0.w += v0.w;
        a1.x += v1.x; a1.y += v1.y; a1.z += v1.z; a1.w += v1.w;
    }
    if (p < e) {
        int s0 = srcs[p];
        float4 v0 = y4[s0 * 8 + chunk];
        a0.x += v0.x; a0.y += v0.y; a0.z += v0.z; a0.w += v0.w;
    }
    a0.x += a1.x; a0.y += a1.y; a0.z += a1.z; a0.w += a1.w;
#pragma unroll
    for (int m = 8; m <= 16; m <<= 1) {
        a0.x += __shfl_xor_sync(0xffffffffu, a0.x, m);
        a0.y += __shfl_xor_sync(0xffffffffu, a0.y, m);
        a0.z += __shfl_xor_sync(0xffffffffu, a0.z, m);
        a0.w += __shfl_xor_sync(0xffffffffu, a0.w, m);
    }
    // channel `lane` = component (lane&3) of the float4 held at lane (lane>>2)
    int srcl = lane >> 2;
    float rx = __shfl_sync(0xffffffffu, a0.x, srcl);
    float ry = __shfl_sync(0xffffffffu, a0.y, srcl);
    float rz = __shfl_sync(0xffffffffu, a0.z, srcl);
    float rw = __shfl_sync(0xffffffffu, a0.w, srcl);
    int s = lane & 3;
    return (s == 0) ? rx : (s == 1) ? ry : (s == 2) ? rz : rw;
}

__global__ __launch_bounds__(256) void k_gather(int layer,
                                                const float* __restrict__ b1,
                                                const float* __restrict__ b2) {
    const float4* ya = layer ? g_y2[0] : g_y1[0];
    const float4* yb = layer ? g_y2[1] : g_y1[1];
    int gw = (blockIdx.x * 256 + threadIdx.x) >> 5;   // exact grid: gw < NN
    int lane = threadIdx.x & 31;
    float a1 = ((const float*)ya)[gw * 32 + lane];
    float a2 = ((const float*)yb)[gw * 32 + lane];
    float s1 = gsum(ya, g_src[0], g_off[0][gw], g_off[0][gw + 1], lane);
    float s2 = gsum(yb, g_src[1], g_off[1][gw], g_off[1][gw + 1], lane);
    g_T1[gw * 32 + lane] = fmaxf(a1 + s1 + __ldg(&b1[lane]), 0.f);
    g_T2[gw * 32 + lane] = fmaxf(a2 + s2 + __ldg(&b2[lane]), 0.f);
}

// ================= mlp1: T -> tm(C1,C2,bp,relu) -> y2 (D1,D2,e1,e2) =================

__global__ __launch_bounds__(256) void k_mlp1() {
    __shared__ float sT1[32 * 36], sT2[32 * 36], sTm[32 * 36];
    __shared__ float sC1[1024], sC2[1024], sD1[1024], sD2[1024];
    __shared__ __align__(16) float sbp[32], se1[32], se2[32];
    int tid = threadIdx.x;
#pragma unroll
    for (int r = 0; r < 4; r++) {
        int t = tid + r * 256;
        sC1[t] = g_C1[t]; sC2[t] = g_C2[t]; sD1[t] = g_D1[t]; sD2[t] = g_D2[t];
    }
    if (tid < 32) { sbp[tid] = g_bp[tid]; se1[tid] = g_e1[tid]; se2[tid] = g_e2[tid]; }
    {
        const float4* gT1 = (const float4*)g_T1 + blockIdx.x * 256;
        const float4* gT2 = (const float4*)g_T2 + blockIdx.x * 256;
        float4 v1 = gT1[tid], v2 = gT2[tid];
        int n = tid >> 3, kk = (tid & 7) * 4;
        *(float4*)(sT1 + n * 36 + kk) = v1;
        *(float4*)(sT2 + n * 36 + kk) = v2;
    }
    __syncthreads();

    int w = tid >> 5, lane = tid & 31;
    int nsub = lane >> 3, o4 = lane & 7;
    int n = w * 4 + nsub;
    const float4* C1v = (const float4*)sC1;
    const float4* C2v = (const float4*)sC2;
    float4 acc = ((const float4*)sbp)[o4];
#pragma unroll
    for (int k = 0; k < 32; k++) {
        float t1 = sT1[n * 36 + k];
        float t2 = sT2[n * 36 + k];
        float4 c1 = C1v[k * 8 + o4];
        float4 c2 = C2v[k * 8 + o4];
        acc.x = fmaf(t1, c1.x, acc.x); acc.y = fmaf(t1, c1.y, acc.y);
        acc.z = fmaf(t1, c1.z, acc.z); acc.w = fmaf(t1, c1.w, acc.w);
        acc.x = fmaf(t2, c2.x, acc.x); acc.y = fmaf(t2, c2.y, acc.y);
        acc.z = fmaf(t2, c2.z, acc.z); acc.w = fmaf(t2, c2.w, acc.w);
    }
    acc.x = fmaxf(acc.x, 0.f); acc.y = fmaxf(acc.y, 0.f);
    acc.z = fmaxf(acc.z, 0.f); acc.w = fmaxf(acc.w, 0.f);
    *(float4*)(sTm + n * 36 + o4 * 4) = acc;
    __syncwarp();

    const float4* D1v = (const float4*)sD1;
    const float4* D2v = (const float4*)sD2;
    float4 y1a = ((const float4*)se1)[o4];
    float4 y2a = ((const float4*)se2)[o4];
#pragma unroll
    for (int k = 0; k < 32; k++) {
        float tm = sTm[n * 36 + k];
        float4 d1 = D1v[k * 8 + o4];
        float4 d2 = D2v[k * 8 + o4];
        y1a.x = fmaf(tm, d1.x, y1a.x); y1a.y = fmaf(tm, d1.y, y1a.y);
        y1a.z = fmaf(tm, d1.z, y1a.z); y1a.w = fmaf(tm, d1.w, y1a.w);
        y2a.x = fmaf(tm, d2.x, y2a.x); y2a.y = fmaf(tm, d2.y, y2a.y);
        y2a.z = fmaf(tm, d2.z, y2a.z); y2a.w = fmaf(tm, d2.w, y2a.w);
    }
    int gn = blockIdx.x * 32 + n;
    g_y2[0][gn * 8 + o4] = y1a;
    g_y2[1][gn * 8 + o4] = y2a;
}

// ================= mlp2: T -> x1,x2(relu) -> tm(M2a,relu) -> dot(v) -> pool =================

__global__ __launch_bounds__(256) void k_mlp2(
    const int* __restrict__ batch, float* __restrict__ out,
    const float* __restrict__ w21b, const float* __restrict__ b21b,
    const float* __restrict__ w22b, const float* __restrict__ b22b,
    const float* __restrict__ m2a,  const float* __restrict__ m2ab)
{
    __shared__ float sT1[32 * 36], sT2[32 * 36], sX1[32 * 36], sX2[32 * 36];
    __shared__ float sW1[1024], sW2[1024], sM[2048];
    __shared__ __align__(16) float sb1[32], sb2[32], sbm[32], sv[32];
    __shared__ float s_c;
    int tid = threadIdx.x;
#pragma unroll
    for (int r = 0; r < 8; r++) {               // FIX: full 2048 elements of m2a
        int t = tid + r * 256;
        sM[t] = m2a[t];
    }
#pragma unroll
    for (int r = 0; r < 4; r++) {
        int t = tid + r * 256;
        sW1[t] = w21b[t]; sW2[t] = w22b[t];
    }
    if (tid < 32) {
        sb1[tid] = b21b[tid]; sb2[tid] = b22b[tid];
        sbm[tid] = m2ab[tid]; sv[tid] = g_v[tid];
    }
    if (tid == 0) s_c = g_c[0];
    {
        const float4* gT1 = (const float4*)g_T1 + blockIdx.x * 256;
        const float4* gT2 = (const float4*)g_T2 + blockIdx.x * 256;
        float4 v1 = gT1[tid], v2 = gT2[tid];
        int n = tid >> 3, kk = (tid & 7) * 4;
        *(float4*)(sT1 + n * 36 + kk) = v1;
        *(float4*)(sT2 + n * 36 + kk) = v2;
    }
    __syncthreads();

    int w = tid >> 5, lane = tid & 31;
    int nsub = lane >> 3, o4 = lane & 7;
    int n = w * 4 + nsub;
    const float4* W1v = (const float4*)sW1;
    const float4* W2v = (const float4*)sW2;
    float4 x1 = ((const float4*)sb1)[o4];
    float4 x2 = ((const float4*)sb2)[o4];
#pragma unroll
    for (int k = 0; k < 32; k++) {
        float t1 = sT1[n * 36 + k];
        float t2 = sT2[n * 36 + k];
        float4 a = W1v[k * 8 + o4];
        float4 b = W2v[k * 8 + o4];
        x1.x = fmaf(t1, a.x, x1.x); x1.y = fmaf(t1, a.y, x1.y);
        x1.z = fmaf(t1, a.z, x1.z); x1.w = fmaf(t1, a.w, x1.w);
        x2.x = fmaf(t2, b.x, x2.x); x2.y = fmaf(t2, b.y, x2.y);
        x2.z = fmaf(t2, b.z, x2.z); x2.w = fmaf(t2, b.w, x2.w);
    }
    x1.x = fmaxf(x1.x, 0.f); x1.y = fmaxf(x1.y, 0.f); x1.z = fmaxf(x1.z, 0.f); x1.w = fmaxf(x1.w, 0.f);
    x2.x = fmaxf(x2.x, 0.f); x2.y = fmaxf(x2.y, 0.f); x2.z = fmaxf(x2.z, 0.f); x2.w = fmaxf(x2.w, 0.f);
    *(float4*)(sX1 + n * 36 + o4 * 4) = x1;
    *(float4*)(sX2 + n * 36 + o4 * 4) = x2;
    __syncwarp();

    const float4* Mv = (const float4*)sM;
    float4 tm = ((const float4*)sbm)[o4];
#pragma unroll
    for (int k = 0; k < 32; k++) {
        float a = sX1[n * 36 + k];
        float b = sX2[n * 36 + k];
        float4 m1 = Mv[k * 8 + o4];
        float4 m2 = Mv[(32 + k) * 8 + o4];
        tm.x = fmaf(a, m1.x, tm.x); tm.y = fmaf(a, m1.y, tm.y);
        tm.z = fmaf(a, m1.z, tm.z); tm.w = fmaf(a, m1.w, tm.w);
        tm.x = fmaf(b, m2.x, tm.x); tm.y = fmaf(b, m2.y, tm.y);
        tm.z = fmaf(b, m2.z, tm.z); tm.w = fmaf(b, m2.w, tm.w);
    }
    tm.x = fmaxf(tm.x, 0.f); tm.y = fmaxf(tm.y, 0.f);
    tm.z = fmaxf(tm.z, 0.f); tm.w = fmaxf(tm.w, 0.f);
    float4 vv = ((const float4*)sv)[o4];
    float p = tm.x * vv.x + tm.y * vv.y + tm.z * vv.z + tm.w * vv.w;
#pragma unroll
    for (int m = 1; m <= 4; m <<= 1) p += __shfl_xor_sync(0xffffffffu, p, m);
    if (o4 == 0) {
        int gn = blockIdx.x * 32 + n;
        atomicAdd(&out[batch[gn]], p + s_c);
    }
}

// ================= launch =================

extern "C" void kernel_launch(void* const* d_in, const int* in_sizes, int n_in,
                              void* d_out, int out_size) {
    const float* x     = (const float*)d_in[0];
    const int*   el    = (const int*)d_in[1];
    const int*   eg    = (const int*)d_in[2];
    const int*   batch = (const int*)d_in[3];
    const float* W[26];
    for (int i = 0; i < 26; i++) W[i] = (const float*)d_in[4 + i];
    float* out = (float*)d_out;

    k_init_compose<<<99, 1024>>>(out, W[25],
                                 W[2], W[6], W[8], W[10], W[12], W[16], W[22],
                                 W[3], W[7], W[9], W[11], W[23], W[24]);

    k_hist_pre1<<<dim3(6250, 3), 256>>>(el, eg, x, W[0], W[4]);

    k_scanfill<<<dim3(NBLK, 2), 1024>>>(el, eg);

    k_gather<<<12500, 256>>>(0, W[1], W[5]);    // 4th launch — profiled

    k_mlp1<<<3125, 256>>>();

    k_gather<<<12500, 256>>>(1, W[13], W[17]);

    k_mlp2<<<3125, 256>>>(batch, out, W[14], W[15], W[18], W[19], W[20], W[21]);
}

// round 6
// speedup vs baseline: 1.5297x; 1.0004x over previous
#include <cuda_runtime.h>

#define NN 100000
#define NE 1600000
#define NG 1000
#define NBLK 98   // ceil(NN/1024)

// ---- static scratch ----
__device__ int            g_cnt[2][NN];
__device__ int            g_off[2][NN + 1];
__device__ unsigned short g_rank[2][NE];
__device__ int            g_src[2][NE];
__device__ int            g_state[2][NBLK];
__device__ int            g_done[2];
__device__ float4         g_y1[2][NN * 8];
__device__ float4         g_y2[2][NN * 8];
__device__ float          g_T1[NN * 32], g_T2[NN * 32];
__device__ float          g_C1[1024], g_C2[1024], g_D1[1024], g_D2[1024];
__device__ __align__(16) float g_bp[32], g_e1[32], g_e2[32], g_v[32];
__device__ float          g_c[1];

// ================= 1) init + compose (fused) =================

__global__ __launch_bounds__(1024) void k_init_compose(
    float* __restrict__ out, const float* __restrict__ lin_b,
    const float* __restrict__ w11b, const float* __restrict__ w12b,
    const float* __restrict__ m1a,  const float* __restrict__ m1b,
    const float* __restrict__ w21a, const float* __restrict__ w22a,
    const float* __restrict__ m2b,
    const float* __restrict__ b11b, const float* __restrict__ b12b,
    const float* __restrict__ m1ab, const float* __restrict__ m1bb,
    const float* __restrict__ m2bb, const float* __restrict__ linW)
{
    if (blockIdx.x < 98) {
        int i = blockIdx.x * 1024 + threadIdx.x;
        if (i < NG) out[i] = lin_b[0];
        if (i < NN) { g_cnt[0][i] = 0; g_cnt[1][i] = 0; }
        if (i < 2 * NBLK) ((int*)g_state)[i] = 0;
        if (i < 2) g_done[i] = 0;
        return;
    }
    __shared__ float s11b[1024], s12b[1024], sm1a[2048], sm1b[1024], s21a[1024], s22a[1024];
    int tid = threadIdx.x;
    s11b[tid] = w11b[tid]; s12b[tid] = w12b[tid]; sm1b[tid] = m1b[tid];
    s21a[tid] = w21a[tid]; s22a[tid] = w22a[tid];
    sm1a[tid] = m1a[tid];  sm1a[tid + 1024] = m1a[tid + 1024];
    __syncthreads();
    int k = tid >> 5, o = tid & 31;
    float c1 = 0.f, c2 = 0.f, d1 = 0.f, d2 = 0.f;
#pragma unroll
    for (int j = 0; j < 32; j++) {
        c1 = fmaf(s11b[k * 32 + j], sm1a[j * 32 + o], c1);
        c2 = fmaf(s12b[k * 32 + j], sm1a[(32 + j) * 32 + o], c2);
        d1 = fmaf(sm1b[k * 32 + j], s21a[j * 32 + o], d1);
        d2 = fmaf(sm1b[k * 32 + j], s22a[j * 32 + o], d2);
    }
    g_C1[tid] = c1; g_C2[tid] = c2; g_D1[tid] = d1; g_D2[tid] = d2;
    if (k == 0) {
        float bp = m1ab[o], e1 = 0.f, e2 = 0.f;
        for (int j = 0; j < 32; j++) {
            bp += b11b[j] * sm1a[j * 32 + o] + b12b[j] * sm1a[(32 + j) * 32 + o];
            e1 += m1bb[j] * s21a[j * 32 + o];
            e2 += m1bb[j] * s22a[j * 32 + o];
        }
        g_bp[o] = bp; g_e1[o] = e1; g_e2[o] = e2;
    }
    if (o == 0) {
        float v = 0.f;
        for (int j = 0; j < 32; j++) v += m2b[k * 32 + j] * linW[j];
        g_v[k] = v;
    }
    if (tid == 0) {
        float c = 0.f;
        for (int j = 0; j < 32; j++) c += m2bb[j] * linW[j];
        g_c[0] = c;
    }
}

// ================= 2) hist =================

__global__ __launch_bounds__(256) void k_hist(const int* __restrict__ el,
                                              const int* __restrict__ eg) {
    int e = blockIdx.x * 256 + threadIdx.x;
    if (e >= NE) return;
    int set = blockIdx.y;
    const int* ei = set ? eg : el;
    g_rank[set][e] = (unsigned short)atomicAdd(&g_cnt[set][ei[NE + e]], 1);
}

// ================= 3) pre-transform y1 = x @ {c11_W1, c12_W1} =================

__global__ __launch_bounds__(256) void k_pre1(const float* __restrict__ x,
                                              const float* __restrict__ w11a,
                                              const float* __restrict__ w12a) {
    __shared__ float sX[32 * 68];
    __shared__ float sW1[2048], sW2[2048];
    int tid = threadIdx.x;
    const float4* gx4 = (const float4*)x + blockIdx.x * 512;
    const float4* gw1 = (const float4*)w11a;
    const float4* gw2 = (const float4*)w12a;
#pragma unroll
    for (int r = 0; r < 2; r++) {
        int i = tid + r * 256;
        float4 v = gx4[i];
        int flat = i * 4, n = flat >> 6, kk = flat & 63;
        *(float4*)(sX + n * 68 + kk) = v;
        ((float4*)sW1)[i] = gw1[i];
        ((float4*)sW2)[i] = gw2[i];
    }
    __syncthreads();

    int w = tid >> 5, lane = tid & 31;
    int nsub = lane >> 3, o4 = lane & 7;
    int n = w * 4 + nsub;
    float4 a1 = make_float4(0.f, 0.f, 0.f, 0.f);
    float4 a2 = make_float4(0.f, 0.f, 0.f, 0.f);
    const float4* W1v = (const float4*)sW1;
    const float4* W2v = (const float4*)sW2;
#pragma unroll
    for (int k = 0; k < 64; k++) {
        float xv = sX[n * 68 + k];
        float4 c1 = W1v[k * 8 + o4];
        float4 c2 = W2v[k * 8 + o4];
        a1.x = fmaf(xv, c1.x, a1.x); a1.y = fmaf(xv, c1.y, a1.y);
        a1.z = fmaf(xv, c1.z, a1.z); a1.w = fmaf(xv, c1.w, a1.w);
        a2.x = fmaf(xv, c2.x, a2.x); a2.y = fmaf(xv, c2.y, a2.y);
        a2.z = fmaf(xv, c2.z, a2.z); a2.w = fmaf(xv, c2.w, a2.w);
    }
    int gn = blockIdx.x * 32 + n;
    g_y1[0][gn * 8 + o4] = a1;
    g_y1[1][gn * 8 + o4] = a2;
}

// ================= 4) scan (decoupled lookback) + barrier + fill =================

__global__ __launch_bounds__(1024, 2) void k_scanfill(const int* __restrict__ el,
                                                      const int* __restrict__ eg) {
    __shared__ int swarp[32];
    __shared__ int s_excl;
    int se = blockIdx.y, blk = blockIdx.x;
    int i = blk * 1024 + threadIdx.x;
    int lane = threadIdx.x & 31, wid = threadIdx.x >> 5;
    int v = (i < NN) ? g_cnt[se][i] : 0;
    int incl = v;
#pragma unroll
    for (int d = 1; d < 32; d <<= 1) {
        int t = __shfl_up_sync(0xffffffffu, incl, d);
        if (lane >= d) incl += t;
    }
    if (lane == 31) swarp[wid] = incl;
    __syncthreads();
    if (wid == 0) {
        int winc = swarp[lane];
#pragma unroll
        for (int d = 1; d < 32; d <<= 1) {
            int t = __shfl_up_sync(0xffffffffu, winc, d);
            if (lane >= d) winc += t;
        }
        swarp[lane] = winc;
    }
    __syncthreads();
    int wexcl = (wid == 0) ? 0 : swarp[wid - 1];
    int btotal = swarp[31];
    int local_incl = wexcl + incl;
    if (threadIdx.x == 0) {
        if (blk == 0) {
            atomicExch(&g_state[se][0], (btotal << 2) | 2);
            s_excl = 0;
        } else {
            atomicExch(&g_state[se][blk], (btotal << 2) | 1);
            int excl = 0, j = blk - 1;
            while (true) {
                int s = atomicAdd(&g_state[se][j], 0);
                int f = s & 3;
                if (f == 0) continue;
                excl += (s >> 2);
                if (f == 2) break;
                j--;
            }
            atomicExch(&g_state[se][blk], ((excl + btotal) << 2) | 2);
            s_excl = excl;
        }
    }
    __syncthreads();
    int ex = s_excl + local_incl - v;
    if (i < NN) {
        g_off[se][i] = ex;
        if (i == NN - 1) g_off[se][NN] = ex + v;
    }
    __threadfence();
    __syncthreads();
    if (threadIdx.x == 0) {
        atomicAdd(&g_done[se], 1);
        while (atomicAdd(&g_done[se], 0) < NBLK) { }
    }
    __syncthreads();
    __threadfence();
    const int* ei = se ? eg : el;
    for (int e = blk * 1024 + threadIdx.x; e < NE; e += NBLK * 1024) {
        int src = ei[e], dst = ei[NE + e];
        g_src[se][g_off[se][dst] + (int)g_rank[se][e]] = src;
    }
}

// ================= 5) gather: warp = node, both edge sets interleaved =================

__global__ __launch_bounds__(256) void k_gather(int layer,
                                                const float* __restrict__ bias1,
                                                const float* __restrict__ bias2) {
    const float4* __restrict__ ya = layer ? g_y2[0] : g_y1[0];
    const float4* __restrict__ yb = layer ? g_y2[1] : g_y1[1];
    float4* __restrict__ T1 = (float4*)g_T1;
    float4* __restrict__ T2 = (float4*)g_T2;
    const int* __restrict__ s0 = g_src[0];
    const int* __restrict__ s1 = g_src[1];

    int gw = (blockIdx.x * 256 + threadIdx.x) >> 5;   // exact grid: gw < NN
    int lane = threadIdx.x & 31;
    int sub = lane >> 3, chunk = lane & 7;

    int e0 = g_off[0][gw + 1], p0 = g_off[0][gw] + sub;
    int e1 = g_off[1][gw + 1], p1 = g_off[1][gw] + sub;

    float4 A0 = make_float4(0.f, 0.f, 0.f, 0.f);
    float4 A1 = make_float4(0.f, 0.f, 0.f, 0.f);
    float4 B0 = make_float4(0.f, 0.f, 0.f, 0.f);
    float4 B1 = make_float4(0.f, 0.f, 0.f, 0.f);

    // fused main loop: 8 edges per set per iteration, 4 independent chains
    while (p0 + 4 < e0 && p1 + 4 < e1) {
        int i00 = __ldcs(&s0[p0]);
        int i01 = __ldcs(&s0[p0 + 4]);
        int i10 = __ldcs(&s1[p1]);
        int i11 = __ldcs(&s1[p1 + 4]);
        float4 v00 = ya[i00 * 8 + chunk];
        float4 v01 = ya[i01 * 8 + chunk];
        float4 v10 = yb[i10 * 8 + chunk];
        float4 v11 = yb[i11 * 8 + chunk];
        A0.x += v00.x; A0.y += v00.y; A0.z += v00.z; A0.w += v00.w;
        A1.x += v01.x; A1.y += v01.y; A1.z += v01.z; A1.w += v01.w;
        B0.x += v10.x; B0.y += v10.y; B0.z += v10.z; B0.w += v10.w;
        B1.x += v11.x; B1.y += v11.y; B1.z += v11.z; B1.w += v11.w;
        p0 += 8; p1 += 8;
    }
    // drain set 0
    for (; p0 < e0; p0 += 4) {
        int s = __ldcs(&s0[p0]);
        float4 v = ya[s * 8 + chunk];
        A0.x += v.x; A0.y += v.y; A0.z += v.z; A0.w += v.w;
    }
    // drain set 1
    for (; p1 < e1; p1 += 4) {
        int s = __ldcs(&s1[p1]);
        float4 v = yb[s * 8 + chunk];
        B0.x += v.x; B0.y += v.y; B0.z += v.z; B0.w += v.w;
    }
    A0.x += A1.x; A0.y += A1.y; A0.z += A1.z; A0.w += A1.w;
    B0.x += B1.x; B0.y += B1.y; B0.z += B1.z; B0.w += B1.w;
#pragma unroll
    for (int m = 8; m <= 16; m <<= 1) {
        A0.x += __shfl_xor_sync(0xffffffffu, A0.x, m);
        A0.y += __shfl_xor_sync(0xffffffffu, A0.y, m);
        A0.z += __shfl_xor_sync(0xffffffffu, A0.z, m);
        A0.w += __shfl_xor_sync(0xffffffffu, A0.w, m);
        B0.x += __shfl_xor_sync(0xffffffffu, B0.x, m);
        B0.y += __shfl_xor_sync(0xffffffffu, B0.y, m);
        B0.z += __shfl_xor_sync(0xffffffffu, B0.z, m);
        B0.w += __shfl_xor_sync(0xffffffffu, B0.w, m);
    }
    // every lane now holds the reduced float4 for channels chunk*4..chunk*4+3
    float4 sa = ya[gw * 8 + chunk];
    float4 sb = yb[gw * 8 + chunk];
    float4 c1 = ((const float4*)bias1)[chunk];
    float4 c2 = ((const float4*)bias2)[chunk];
    float4 t1, t2;
    t1.x = fmaxf(A0.x + sa.x + c1.x, 0.f); t1.y = fmaxf(A0.y + sa.y + c1.y, 0.f);
    t1.z = fmaxf(A0.z + sa.z + c1.z, 0.f); t1.w = fmaxf(A0.w + sa.w + c1.w, 0.f);
    t2.x = fmaxf(B0.x + sb.x + c2.x, 0.f); t2.y = fmaxf(B0.y + sb.y + c2.y, 0.f);
    t2.z = fmaxf(B0.z + sb.z + c2.z, 0.f); t2.w = fmaxf(B0.w + sb.w + c2.w, 0.f);
    if (sub == 0) T1[gw * 8 + chunk] = t1;
    else if (sub == 1) T2[gw * 8 + chunk] = t2;
}

// ================= 6) mlp1: T -> tm(C1,C2,bp,relu) -> y2 (D1,D2,e1,e2) =================

__global__ __launch_bounds__(256) void k_mlp1() {
    __shared__ float sT1[32 * 36], sT2[32 * 36], sTm[32 * 36];
    __shared__ float sC1[1024], sC2[1024], sD1[1024], sD2[1024];
    __shared__ __align__(16) float sbp[32], se1[32], se2[32];
    int tid = threadIdx.x;
#pragma unroll
    for (int r = 0; r < 4; r++) {
        int t = tid + r * 256;
        sC1[t] = g_C1[t]; sC2[t] = g_C2[t]; sD1[t] = g_D1[t]; sD2[t] = g_D2[t];
    }
    if (tid < 32) { sbp[tid] = g_bp[tid]; se1[tid] = g_e1[tid]; se2[tid] = g_e2[tid]; }
    {
        const float4* gT1 = (const float4*)g_T1 + blockIdx.x * 256;
        const float4* gT2 = (const float4*)g_T2 + blockIdx.x * 256;
        float4 v1 = gT1[tid], v2 = gT2[tid];
        int n = tid >> 3, kk = (tid & 7) * 4;
        *(float4*)(sT1 + n * 36 + kk) = v1;
        *(float4*)(sT2 + n * 36 + kk) = v2;
    }
    __syncthreads();

    int w = tid >> 5, lane = tid & 31;
    int nsub = lane >> 3, o4 = lane & 7;
    int n = w * 4 + nsub;
    const float4* C1v = (const float4*)sC1;
    const float4* C2v = (const float4*)sC2;
    float4 acc = ((const float4*)sbp)[o4];
#pragma unroll
    for (int k = 0; k < 32; k++) {
        float t1 = sT1[n * 36 + k];
        float t2 = sT2[n * 36 + k];
        float4 c1 = C1v[k * 8 + o4];
        float4 c2 = C2v[k * 8 + o4];
        acc.x = fmaf(t1, c1.x, acc.x); acc.y = fmaf(t1, c1.y, acc.y);
        acc.z = fmaf(t1, c1.z, acc.z); acc.w = fmaf(t1, c1.w, acc.w);
        acc.x = fmaf(t2, c2.x, acc.x); acc.y = fmaf(t2, c2.y, acc.y);
        acc.z = fmaf(t2, c2.z, acc.z); acc.w = fmaf(t2, c2.w, acc.w);
    }
    acc.x = fmaxf(acc.x, 0.f); acc.y = fmaxf(acc.y, 0.f);
    acc.z = fmaxf(acc.z, 0.f); acc.w = fmaxf(acc.w, 0.f);
    *(float4*)(sTm + n * 36 + o4 * 4) = acc;
    __syncwarp();

    const float4* D1v = (const float4*)sD1;
    const float4* D2v = (const float4*)sD2;
    float4 y1a = ((const float4*)se1)[o4];
    float4 y2a = ((const float4*)se2)[o4];
#pragma unroll
    for (int k = 0; k < 32; k++) {
        float tm = sTm[n * 36 + k];
        float4 d1 = D1v[k * 8 + o4];
        float4 d2 = D2v[k * 8 + o4];
        y1a.x = fmaf(tm, d1.x, y1a.x); y1a.y = fmaf(tm, d1.y, y1a.y);
        y1a.z = fmaf(tm, d1.z, y1a.z); y1a.w = fmaf(tm, d1.w, y1a.w);
        y2a.x = fmaf(tm, d2.x, y2a.x); y2a.y = fmaf(tm, d2.y, y2a.y);
        y2a.z = fmaf(tm, d2.z, y2a.z); y2a.w = fmaf(tm, d2.w, y2a.w);
    }
    int gn = blockIdx.x * 32 + n;
    g_y2[0][gn * 8 + o4] = y1a;
    g_y2[1][gn * 8 + o4] = y2a;
}

// ================= 7) mlp2: T -> x1,x2(relu) -> tm(M2a,relu) -> dot(v) -> pool =================

__global__ __launch_bounds__(256) void k_mlp2(
    const int* __restrict__ batch, float* __restrict__ out,
    const float* __restrict__ w21b, const float* __restrict__ b21b,
    const float* __restrict__ w22b, const float* __restrict__ b22b,
    const float* __restrict__ m2a,  const float* __restrict__ m2ab)
{
    __shared__ float sT1[32 * 36], sT2[32 * 36], sX1[32 * 36], sX2[32 * 36];
    __shared__ float sW1[1024], sW2[1024], sM[2048];
    __shared__ __align__(16) float sb1[32], sb2[32], sbm[32], sv[32];
    __shared__ float s_c;
    int tid = threadIdx.x;
#pragma unroll
    for (int r = 0; r < 8; r++) {
        int t = tid + r * 256;
        sM[t] = m2a[t];
    }
#pragma unroll
    for (int r = 0; r < 4; r++) {
        int t = tid + r * 256;
        sW1[t] = w21b[t]; sW2[t] = w22b[t];
    }
    if (tid < 32) {
        sb1[tid] = b21b[tid]; sb2[tid] = b22b[tid];
        sbm[tid] = m2ab[tid]; sv[tid] = g_v[tid];
    }
    if (tid == 0) s_c = g_c[0];
    {
        const float4* gT1 = (const float4*)g_T1 + blockIdx.x * 256;
        const float4* gT2 = (const float4*)g_T2 + blockIdx.x * 256;
        float4 v1 = gT1[tid], v2 = gT2[tid];
        int n = tid >> 3, kk = (tid & 7) * 4;
        *(float4*)(sT1 + n * 36 + kk) = v1;
        *(float4*)(sT2 + n * 36 + kk) = v2;
    }
    __syncthreads();

    int w = tid >> 5, lane = tid & 31;
    int nsub = lane >> 3, o4 = lane & 7;
    int n = w * 4 + nsub;
    const float4* W1v = (const float4*)sW1;
    const float4* W2v = (const float4*)sW2;
    float4 x1 = ((const float4*)sb1)[o4];
    float4 x2 = ((const float4*)sb2)[o4];
#pragma unroll
    for (int k = 0; k < 32; k++) {
        float t1 = sT1[n * 36 + k];
        float t2 = sT2[n * 36 + k];
        float4 a = W1v[k * 8 + o4];
        float4 b = W2v[k * 8 + o4];
        x1.x = fmaf(t1, a.x, x1.x); x1.y = fmaf(t1, a.y, x1.y);
        x1.z = fmaf(t1, a.z, x1.z); x1.w = fmaf(t1, a.w, x1.w);
        x2.x = fmaf(t2, b.x, x2.x); x2.y = fmaf(t2, b.y, x2.y);
        x2.z = fmaf(t2, b.z, x2.z); x2.w = fmaf(t2, b.w, x2.w);
    }
    x1.x = fmaxf(x1.x, 0.f); x1.y = fmaxf(x1.y, 0.f); x1.z = fmaxf(x1.z, 0.f); x1.w = fmaxf(x1.w, 0.f);
    x2.x = fmaxf(x2.x, 0.f); x2.y = fmaxf(x2.y, 0.f); x2.z = fmaxf(x2.z, 0.f); x2.w = fmaxf(x2.w, 0.f);
    *(float4*)(sX1 + n * 36 + o4 * 4) = x1;
    *(float4*)(sX2 + n * 36 + o4 * 4) = x2;
    __syncwarp();

    const float4* Mv = (const float4*)sM;
    float4 tm = ((const float4*)sbm)[o4];
#pragma unroll
    for (int k = 0; k < 32; k++) {
        float a = sX1[n * 36 + k];
        float b = sX2[n * 36 + k];
        float4 m1 = Mv[k * 8 + o4];
        float4 m2 = Mv[(32 + k) * 8 + o4];
        tm.x = fmaf(a, m1.x, tm.x); tm.y = fmaf(a, m1.y, tm.y);
        tm.z = fmaf(a, m1.z, tm.z); tm.w = fmaf(a, m1.w, tm.w);
        tm.x = fmaf(b, m2.x, tm.x); tm.y = fmaf(b, m2.y, tm.y);
        tm.z = fmaf(b, m2.z, tm.z); tm.w = fmaf(b, m2.w, tm.w);
    }
    tm.x = fmaxf(tm.x, 0.f); tm.y = fmaxf(tm.y, 0.f);
    tm.z = fmaxf(tm.z, 0.f); tm.w = fmaxf(tm.w, 0.f);
    float4 vv = ((const float4*)sv)[o4];
    float p = tm.x * vv.x + tm.y * vv.y + tm.z * vv.z + tm.w * vv.w;
#pragma unroll
    for (int m = 1; m <= 4; m <<= 1) p += __shfl_xor_sync(0xffffffffu, p, m);
    if (o4 == 0) {
        int gn = blockIdx.x * 32 + n;
        atomicAdd(&out[batch[gn]], p + s_c);
    }
}

// ================= launch =================

extern "C" void kernel_launch(void* const* d_in, const int* in_sizes, int n_in,
                              void* d_out, int out_size) {
    const float* x     = (const float*)d_in[0];
    const int*   el    = (const int*)d_in[1];
    const int*   eg    = (const int*)d_in[2];
    const int*   batch = (const int*)d_in[3];
    const float* W[26];
    for (int i = 0; i < 26; i++) W[i] = (const float*)d_in[4 + i];
    float* out = (float*)d_out;

    k_init_compose<<<99, 1024>>>(out, W[25],
                                 W[2], W[6], W[8], W[10], W[12], W[16], W[22],
                                 W[3], W[7], W[9], W[11], W[23], W[24]);            // 1

    k_hist<<<dim3(6250, 2), 256>>>(el, eg);                                        // 2

    k_pre1<<<3125, 256>>>(x, W[0], W[4]);                                          // 3

    k_scanfill<<<dim3(NBLK, 2), 1024>>>(el, eg);                                   // 4 — profiled

    k_gather<<<12500, 256>>>(0, W[1], W[5]);                                       // 5

    k_mlp1<<<3125, 256>>>();                                                       // 6

    k_gather<<<12500, 256>>>(1, W[13], W[17]);                                     // 7

    k_mlp2<<<3125, 256>>>(batch, out, W[14], W[15], W[18], W[19], W[20], W[21]);   // 8
}

// round 7
// speedup vs baseline: 1.5987x; 1.0451x over previous
#include <cuda_runtime.h>

#define NN 100000
#define NE 1600000
#define NG 1000
#define NBLK 98   // ceil(NN/1024)

// ---- static scratch ----
__device__ int            g_cnt[2][NN];
__device__ int            g_off[2][NN + 1];
__device__ unsigned short g_rank[2][NE];
__device__ int            g_src[2][NE];
__device__ int            g_state[2][NBLK];
__device__ int            g_done[2];
__device__ float4         g_y1[2][NN * 8];
__device__ float4         g_y2[2][NN * 8];
__device__ float          g_T1[NN * 32], g_T2[NN * 32];
__device__ float          g_C1[1024], g_C2[1024], g_D1[1024], g_D2[1024];
__device__ __align__(16) float g_bp[32], g_e1[32], g_e2[32], g_v[32];
__device__ float          g_c[1];

// ================= 1) init + compose (fused) =================

__global__ __launch_bounds__(1024) void k_init_compose(
    float* __restrict__ out, const float* __restrict__ lin_b,
    const float* __restrict__ w11b, const float* __restrict__ w12b,
    const float* __restrict__ m1a,  const float* __restrict__ m1b,
    const float* __restrict__ w21a, const float* __restrict__ w22a,
    const float* __restrict__ m2b,
    const float* __restrict__ b11b, const float* __restrict__ b12b,
    const float* __restrict__ m1ab, const float* __restrict__ m1bb,
    const float* __restrict__ m2bb, const float* __restrict__ linW)
{
    if (blockIdx.x < 98) {
        int i = blockIdx.x * 1024 + threadIdx.x;
        if (i < NG) out[i] = lin_b[0];
        if (i < NN) { g_cnt[0][i] = 0; g_cnt[1][i] = 0; }
        if (i < 2 * NBLK) ((int*)g_state)[i] = 0;
        if (i < 2) g_done[i] = 0;
        return;
    }
    __shared__ float s11b[1024], s12b[1024], sm1a[2048], sm1b[1024], s21a[1024], s22a[1024];
    int tid = threadIdx.x;
    s11b[tid] = w11b[tid]; s12b[tid] = w12b[tid]; sm1b[tid] = m1b[tid];
    s21a[tid] = w21a[tid]; s22a[tid] = w22a[tid];
    sm1a[tid] = m1a[tid];  sm1a[tid + 1024] = m1a[tid + 1024];
    __syncthreads();
    int k = tid >> 5, o = tid & 31;
    float c1 = 0.f, c2 = 0.f, d1 = 0.f, d2 = 0.f;
#pragma unroll
    for (int j = 0; j < 32; j++) {
        c1 = fmaf(s11b[k * 32 + j], sm1a[j * 32 + o], c1);
        c2 = fmaf(s12b[k * 32 + j], sm1a[(32 + j) * 32 + o], c2);
        d1 = fmaf(sm1b[k * 32 + j], s21a[j * 32 + o], d1);
        d2 = fmaf(sm1b[k * 32 + j], s22a[j * 32 + o], d2);
    }
    g_C1[tid] = c1; g_C2[tid] = c2; g_D1[tid] = d1; g_D2[tid] = d2;
    if (k == 0) {
        float bp = m1ab[o], e1 = 0.f, e2 = 0.f;
        for (int j = 0; j < 32; j++) {
            bp += b11b[j] * sm1a[j * 32 + o] + b12b[j] * sm1a[(32 + j) * 32 + o];
            e1 += m1bb[j] * s21a[j * 32 + o];
            e2 += m1bb[j] * s22a[j * 32 + o];
        }
        g_bp[o] = bp; g_e1[o] = e1; g_e2[o] = e2;
    }
    if (o == 0) {
        float v = 0.f;
        for (int j = 0; j < 32; j++) v += m2b[k * 32 + j] * linW[j];
        g_v[k] = v;
    }
    if (tid == 0) {
        float c = 0.f;
        for (int j = 0; j < 32; j++) c += m2bb[j] * linW[j];
        g_c[0] = c;
    }
}

// ================= 2) hist + pre-transform (fused via grid.y) =================

__global__ __launch_bounds__(256) void k_hist_pre1(
    const int* __restrict__ el, const int* __restrict__ eg,
    const float* __restrict__ x,
    const float* __restrict__ w11a, const float* __restrict__ w12a)
{
    __shared__ float sX[32 * 68];
    __shared__ float sW1[2048], sW2[2048];

    if (blockIdx.y < 2) {
        int e = blockIdx.x * 256 + threadIdx.x;
        if (e >= NE) return;
        int set = blockIdx.y;
        const int* ei = set ? eg : el;
        g_rank[set][e] = (unsigned short)atomicAdd(&g_cnt[set][ei[NE + e]], 1);
        return;
    }
    if (blockIdx.x >= 3125) return;
    int tid = threadIdx.x;
    const float4* gx4 = (const float4*)x + blockIdx.x * 512;
    const float4* gw1 = (const float4*)w11a;
    const float4* gw2 = (const float4*)w12a;
#pragma unroll
    for (int r = 0; r < 2; r++) {
        int i = tid + r * 256;
        float4 v = gx4[i];
        int flat = i * 4, n = flat >> 6, kk = flat & 63;
        *(float4*)(sX + n * 68 + kk) = v;
        ((float4*)sW1)[i] = gw1[i];
        ((float4*)sW2)[i] = gw2[i];
    }
    __syncthreads();

    int w = tid >> 5, lane = tid & 31;
    int nsub = lane >> 3, o4 = lane & 7;
    int n = w * 4 + nsub;
    float4 a1 = make_float4(0.f, 0.f, 0.f, 0.f);
    float4 a2 = make_float4(0.f, 0.f, 0.f, 0.f);
    const float4* W1v = (const float4*)sW1;
    const float4* W2v = (const float4*)sW2;
#pragma unroll
    for (int k = 0; k < 64; k++) {
        float xv = sX[n * 68 + k];
        float4 c1 = W1v[k * 8 + o4];
        float4 c2 = W2v[k * 8 + o4];
        a1.x = fmaf(xv, c1.x, a1.x); a1.y = fmaf(xv, c1.y, a1.y);
        a1.z = fmaf(xv, c1.z, a1.z); a1.w = fmaf(xv, c1.w, a1.w);
        a2.x = fmaf(xv, c2.x, a2.x); a2.y = fmaf(xv, c2.y, a2.y);
        a2.z = fmaf(xv, c2.z, a2.z); a2.w = fmaf(xv, c2.w, a2.w);
    }
    int gn = blockIdx.x * 32 + n;
    g_y1[0][gn * 8 + o4] = a1;
    g_y1[1][gn * 8 + o4] = a2;
}

// ================= 3) scan (decoupled lookback) + barrier + fill =================

__global__ __launch_bounds__(1024, 2) void k_scanfill(const int* __restrict__ el,
                                                      const int* __restrict__ eg) {
    __shared__ int swarp[32];
    __shared__ int s_excl;
    int se = blockIdx.y, blk = blockIdx.x;
    int i = blk * 1024 + threadIdx.x;
    int lane = threadIdx.x & 31, wid = threadIdx.x >> 5;
    int v = (i < NN) ? g_cnt[se][i] : 0;
    int incl = v;
#pragma unroll
    for (int d = 1; d < 32; d <<= 1) {
        int t = __shfl_up_sync(0xffffffffu, incl, d);
        if (lane >= d) incl += t;
    }
    if (lane == 31) swarp[wid] = incl;
    __syncthreads();
    if (wid == 0) {
        int winc = swarp[lane];
#pragma unroll
        for (int d = 1; d < 32; d <<= 1) {
            int t = __shfl_up_sync(0xffffffffu, winc, d);
            if (lane >= d) winc += t;
        }
        swarp[lane] = winc;
    }
    __syncthreads();
    int wexcl = (wid == 0) ? 0 : swarp[wid - 1];
    int btotal = swarp[31];
    int local_incl = wexcl + incl;
    if (threadIdx.x == 0) {
        if (blk == 0) {
            atomicExch(&g_state[se][0], (btotal << 2) | 2);
            s_excl = 0;
        } else {
            atomicExch(&g_state[se][blk], (btotal << 2) | 1);
            int excl = 0, j = blk - 1;
            while (true) {
                int s = atomicAdd(&g_state[se][j], 0);
                int f = s & 3;
                if (f == 0) continue;
                excl += (s >> 2);
                if (f == 2) break;
                j--;
            }
            atomicExch(&g_state[se][blk], ((excl + btotal) << 2) | 2);
            s_excl = excl;
        }
    }
    __syncthreads();
    int ex = s_excl + local_incl - v;
    if (i < NN) {
        g_off[se][i] = ex;
        if (i == NN - 1) g_off[se][NN] = ex + v;
    }
    __threadfence();
    __syncthreads();
    if (threadIdx.x == 0) {
        atomicAdd(&g_done[se], 1);
        while (atomicAdd(&g_done[se], 0) < NBLK) { }
    }
    __syncthreads();
    __threadfence();
    const int* ei = se ? eg : el;
    for (int e = blk * 1024 + threadIdx.x; e < NE; e += NBLK * 1024) {
        int src = ei[e], dst = ei[NE + e];
        g_src[se][g_off[se][dst] + (int)g_rank[se][e]] = src;
    }
}

// ================= 4) gather: warp = node, batched index prefetch =================
// Phase 1: up to 8 idx slots per set (32 edges/set) loaded as one batch.
// Phase 2: all data loads issued as one batch. Rare tail loops for degree > 32.

__global__ __launch_bounds__(256) void k_gather(int layer,
                                                const float* __restrict__ bias1,
                                                const float* __restrict__ bias2) {
    const float4* __restrict__ ya = layer ? g_y2[0] : g_y1[0];
    const float4* __restrict__ yb = layer ? g_y2[1] : g_y1[1];
    float4* __restrict__ T1 = (float4*)g_T1;
    float4* __restrict__ T2 = (float4*)g_T2;
    const int* __restrict__ s0 = g_src[0];
    const int* __restrict__ s1 = g_src[1];

    int gw = (blockIdx.x * 256 + threadIdx.x) >> 5;   // exact grid: gw < NN
    int lane = threadIdx.x & 31;
    int sub = lane >> 3, chunk = lane & 7;

    int b0 = g_off[0][gw] + sub, e0 = g_off[0][gw + 1];
    int b1 = g_off[1][gw] + sub, e1 = g_off[1][gw + 1];

    // ---- phase 1: batched index loads (independent) ----
    int ia[8], ib[8];
#pragma unroll
    for (int j = 0; j < 8; j++) {
        int p = b0 + 4 * j;
        ia[j] = (p < e0) ? __ldcs(&s0[p]) : -1;
    }
#pragma unroll
    for (int j = 0; j < 8; j++) {
        int p = b1 + 4 * j;
        ib[j] = (p < e1) ? __ldcs(&s1[p]) : -1;
    }

    // ---- phase 2: batched data loads (independent) ----
    float4 A = make_float4(0.f, 0.f, 0.f, 0.f);
    float4 B = make_float4(0.f, 0.f, 0.f, 0.f);
#pragma unroll
    for (int j = 0; j < 8; j++) {
        if (ia[j] >= 0) {
            float4 v = ya[ia[j] * 8 + chunk];
            A.x += v.x; A.y += v.y; A.z += v.z; A.w += v.w;
        }
    }
#pragma unroll
    for (int j = 0; j < 8; j++) {
        if (ib[j] >= 0) {
            float4 v = yb[ib[j] * 8 + chunk];
            B.x += v.x; B.y += v.y; B.z += v.z; B.w += v.w;
        }
    }
    // ---- rare tails (degree > 32) ----
    for (int p = b0 + 32; p < e0; p += 4) {
        int s = __ldcs(&s0[p]);
        float4 v = ya[s * 8 + chunk];
        A.x += v.x; A.y += v.y; A.z += v.z; A.w += v.w;
    }
    for (int p = b1 + 32; p < e1; p += 4) {
        int s = __ldcs(&s1[p]);
        float4 v = yb[s * 8 + chunk];
        B.x += v.x; B.y += v.y; B.z += v.z; B.w += v.w;
    }

    // cross-sub reduction: after xor 8,16 every lane holds the full sum for its chunk
#pragma unroll
    for (int m = 8; m <= 16; m <<= 1) {
        A.x += __shfl_xor_sync(0xffffffffu, A.x, m);
        A.y += __shfl_xor_sync(0xffffffffu, A.y, m);
        A.z += __shfl_xor_sync(0xffffffffu, A.z, m);
        A.w += __shfl_xor_sync(0xffffffffu, A.w, m);
        B.x += __shfl_xor_sync(0xffffffffu, B.x, m);
        B.y += __shfl_xor_sync(0xffffffffu, B.y, m);
        B.z += __shfl_xor_sync(0xffffffffu, B.z, m);
        B.w += __shfl_xor_sync(0xffffffffu, B.w, m);
    }
    float4 sa = ya[gw * 8 + chunk];
    float4 sb = yb[gw * 8 + chunk];
    float4 c1 = ((const float4*)bias1)[chunk];
    float4 c2 = ((const float4*)bias2)[chunk];
    float4 t1, t2;
    t1.x = fmaxf(A.x + sa.x + c1.x, 0.f); t1.y = fmaxf(A.y + sa.y + c1.y, 0.f);
    t1.z = fmaxf(A.z + sa.z + c1.z, 0.f); t1.w = fmaxf(A.w + sa.w + c1.w, 0.f);
    t2.x = fmaxf(B.x + sb.x + c2.x, 0.f); t2.y = fmaxf(B.y + sb.y + c2.y, 0.f);
    t2.z = fmaxf(B.z + sb.z + c2.z, 0.f); t2.w = fmaxf(B.w + sb.w + c2.w, 0.f);
    if (sub == 0) T1[gw * 8 + chunk] = t1;
    else if (sub == 1) T2[gw * 8 + chunk] = t2;
}

// ================= 5) mlp1: T -> tm(C1,C2,bp,relu) -> y2 (D1,D2,e1,e2) =================

__global__ __launch_bounds__(256) void k_mlp1() {
    __shared__ float sT1[32 * 36], sT2[32 * 36], sTm[32 * 36];
    __shared__ float sC1[1024], sC2[1024], sD1[1024], sD2[1024];
    __shared__ __align__(16) float sbp[32], se1[32], se2[32];
    int tid = threadIdx.x;
#pragma unroll
    for (int r = 0; r < 4; r++) {
        int t = tid + r * 256;
        sC1[t] = g_C1[t]; sC2[t] = g_C2[t]; sD1[t] = g_D1[t]; sD2[t] = g_D2[t];
    }
    if (tid < 32) { sbp[tid] = g_bp[tid]; se1[tid] = g_e1[tid]; se2[tid] = g_e2[tid]; }
    {
        const float4* gT1 = (const float4*)g_T1 + blockIdx.x * 256;
        const float4* gT2 = (const float4*)g_T2 + blockIdx.x * 256;
        float4 v1 = gT1[tid], v2 = gT2[tid];
        int n = tid >> 3, kk = (tid & 7) * 4;
        *(float4*)(sT1 + n * 36 + kk) = v1;
        *(float4*)(sT2 + n * 36 + kk) = v2;
    }
    __syncthreads();

    int w = tid >> 5, lane = tid & 31;
    int nsub = lane >> 3, o4 = lane & 7;
    int n = w * 4 + nsub;
    const float4* C1v = (const float4*)sC1;
    const float4* C2v = (const float4*)sC2;
    float4 acc = ((const float4*)sbp)[o4];
#pragma unroll
    for (int k = 0; k < 32; k++) {
        float t1 = sT1[n * 36 + k];
        float t2 = sT2[n * 36 + k];
        float4 c1 = C1v[k * 8 + o4];
        float4 c2 = C2v[k * 8 + o4];
        acc.x = fmaf(t1, c1.x, acc.x); acc.y = fmaf(t1, c1.y, acc.y);
        acc.z = fmaf(t1, c1.z, acc.z); acc.w = fmaf(t1, c1.w, acc.w);
        acc.x = fmaf(t2, c2.x, acc.x); acc.y = fmaf(t2, c2.y, acc.y);
        acc.z = fmaf(t2, c2.z, acc.z); acc.w = fmaf(t2, c2.w, acc.w);
    }
    acc.x = fmaxf(acc.x, 0.f); acc.y = fmaxf(acc.y, 0.f);
    acc.z = fmaxf(acc.z, 0.f); acc.w = fmaxf(acc.w, 0.f);
    *(float4*)(sTm + n * 36 + o4 * 4) = acc;
    __syncwarp();

    const float4* D1v = (const float4*)sD1;
    const float4* D2v = (const float4*)sD2;
    float4 y1a = ((const float4*)se1)[o4];
    float4 y2a = ((const float4*)se2)[o4];
#pragma unroll
    for (int k = 0; k < 32; k++) {
        float tm = sTm[n * 36 + k];
        float4 d1 = D1v[k * 8 + o4];
        float4 d2 = D2v[k * 8 + o4];
        y1a.x = fmaf(tm, d1.x, y1a.x); y1a.y = fmaf(tm, d1.y, y1a.y);
        y1a.z = fmaf(tm, d1.z, y1a.z); y1a.w = fmaf(tm, d1.w, y1a.w);
        y2a.x = fmaf(tm, d2.x, y2a.x); y2a.y = fmaf(tm, d2.y, y2a.y);
        y2a.z = fmaf(tm, d2.z, y2a.z); y2a.w = fmaf(tm, d2.w, y2a.w);
    }
    int gn = blockIdx.x * 32 + n;
    g_y2[0][gn * 8 + o4] = y1a;
    g_y2[1][gn * 8 + o4] = y2a;
}

// ================= 6) mlp2: T -> x1,x2(relu) -> tm(M2a,relu) -> dot(v) -> pool =================

__global__ __launch_bounds__(256) void k_mlp2(
    const int* __restrict__ batch, float* __restrict__ out,
    const float* __restrict__ w21b, const float* __restrict__ b21b,
    const float* __restrict__ w22b, const float* __restrict__ b22b,
    const float* __restrict__ m2a,  const float* __restrict__ m2ab)
{
    __shared__ float sT1[32 * 36], sT2[32 * 36], sX1[32 * 36], sX2[32 * 36];
    __shared__ float sW1[1024], sW2[1024], sM[2048];
    __shared__ __align__(16) float sb1[32], sb2[32], sbm[32], sv[32];
    __shared__ float s_c;
    int tid = threadIdx.x;
#pragma unroll
    for (int r = 0; r < 8; r++) {
        int t = tid + r * 256;
        sM[t] = m2a[t];
    }
#pragma unroll
    for (int r = 0; r < 4; r++) {
        int t = tid + r * 256;
        sW1[t] = w21b[t]; sW2[t] = w22b[t];
    }
    if (tid < 32) {
        sb1[tid] = b21b[tid]; sb2[tid] = b22b[tid];
        sbm[tid] = m2ab[tid]; sv[tid] = g_v[tid];
    }
    if (tid == 0) s_c = g_c[0];
    {
        const float4* gT1 = (const float4*)g_T1 + blockIdx.x * 256;
        const float4* gT2 = (const float4*)g_T2 + blockIdx.x * 256;
        float4 v1 = gT1[tid], v2 = gT2[tid];
        int n = tid >> 3, kk = (tid & 7) * 4;
        *(float4*)(sT1 + n * 36 + kk) = v1;
        *(float4*)(sT2 + n * 36 + kk) = v2;
    }
    __syncthreads();

    int w = tid >> 5, lane = tid & 31;
    int nsub = lane >> 3, o4 = lane & 7;
    int n = w * 4 + nsub;
    const float4* W1v = (const float4*)sW1;
    const float4* W2v = (const float4*)sW2;
    float4 x1 = ((const float4*)sb1)[o4];
    float4 x2 = ((const float4*)sb2)[o4];
#pragma unroll
    for (int k = 0; k < 32; k++) {
        float t1 = sT1[n * 36 + k];
        float t2 = sT2[n * 36 + k];
        float4 a = W1v[k * 8 + o4];
        float4 b = W2v[k * 8 + o4];
        x1.x = fmaf(t1, a.x, x1.x); x1.y = fmaf(t1, a.y, x1.y);
        x1.z = fmaf(t1, a.z, x1.z); x1.w = fmaf(t1, a.w, x1.w);
        x2.x = fmaf(t2, b.x, x2.x); x2.y = fmaf(t2, b.y, x2.y);
        x2.z = fmaf(t2, b.z, x2.z); x2.w = fmaf(t2, b.w, x2.w);
    }
    x1.x = fmaxf(x1.x, 0.f); x1.y = fmaxf(x1.y, 0.f); x1.z = fmaxf(x1.z, 0.f); x1.w = fmaxf(x1.w, 0.f);
    x2.x = fmaxf(x2.x, 0.f); x2.y = fmaxf(x2.y, 0.f); x2.z = fmaxf(x2.z, 0.f); x2.w = fmaxf(x2.w, 0.f);
    *(float4*)(sX1 + n * 36 + o4 * 4) = x1;
    *(float4*)(sX2 + n * 36 + o4 * 4) = x2;
    __syncwarp();

    const float4* Mv = (const float4*)sM;
    float4 tm = ((const float4*)sbm)[o4];
#pragma unroll
    for (int k = 0; k < 32; k++) {
        float a = sX1[n * 36 + k];
        float b = sX2[n * 36 + k];
        float4 m1 = Mv[k * 8 + o4];
        float4 m2 = Mv[(32 + k) * 8 + o4];
        tm.x = fmaf(a, m1.x, tm.x); tm.y = fmaf(a, m1.y, tm.y);
        tm.z = fmaf(a, m1.z, tm.z); tm.w = fmaf(a, m1.w, tm.w);
        tm.x = fmaf(b, m2.x, tm.x); tm.y = fmaf(b, m2.y, tm.y);
        tm.z = fmaf(b, m2.z, tm.z); tm.w = fmaf(b, m2.w, tm.w);
    }
    tm.x = fmaxf(tm.x, 0.f); tm.y = fmaxf(tm.y, 0.f);
    tm.z = fmaxf(tm.z, 0.f); tm.w = fmaxf(tm.w, 0.f);
    float4 vv = ((const float4*)sv)[o4];
    float p = tm.x * vv.x + tm.y * vv.y + tm.z * vv.z + tm.w * vv.w;
#pragma unroll
    for (int m = 1; m <= 4; m <<= 1) p += __shfl_xor_sync(0xffffffffu, p, m);
    if (o4 == 0) {
        int gn = blockIdx.x * 32 + n;
        atomicAdd(&out[batch[gn]], p + s_c);
    }
}

// ================= launch =================

extern "C" void kernel_launch(void* const* d_in, const int* in_sizes, int n_in,
                              void* d_out, int out_size) {
    const float* x     = (const float*)d_in[0];
    const int*   el    = (const int*)d_in[1];
    const int*   eg    = (const int*)d_in[2];
    const int*   batch = (const int*)d_in[3];
    const float* W[26];
    for (int i = 0; i < 26; i++) W[i] = (const float*)d_in[4 + i];
    float* out = (float*)d_out;

    k_init_compose<<<99, 1024>>>(out, W[25],
                                 W[2], W[6], W[8], W[10], W[12], W[16], W[22],
                                 W[3], W[7], W[9], W[11], W[23], W[24]);            // 1

    k_hist_pre1<<<dim3(6250, 3), 256>>>(el, eg, x, W[0], W[4]);                    // 2

    k_scanfill<<<dim3(NBLK, 2), 1024>>>(el, eg);                                   // 3

    k_gather<<<12500, 256>>>(0, W[1], W[5]);                                       // 4 — profiled

    k_mlp1<<<3125, 256>>>();                                                       // 5

    k_gather<<<12500, 256>>>(1, W[13], W[17]);                                     // 6

    k_mlp2<<<3125, 256>>>(batch, out, W[14], W[15], W[18], W[19], W[20], W[21]);   // 7
}